// round 2
// baseline (speedup 1.0000x reference)
#include <cuda_runtime.h>
#include <math_constants.h>

// ---------------------------------------------------------------------------
// Problem constants
// ---------------------------------------------------------------------------
#define BATCH 4
#define NPTS  1024
#define CIN   768
#define KNN   20
#define HDIM  1152    // 512 + 256 + 128 + 256
#define PCH   32      // pooling chunks
#define EPS   1e-5f

// ---------------------------------------------------------------------------
// Scratch (device globals; no allocation allowed)
// ---------------------------------------------------------------------------
__device__ float g_XT [BATCH * NPTS * CIN];     // x transposed: (B, N, C)
__device__ float g_G  [BATCH * NPTS * NPTS];    // gram matrix
__device__ int   g_idx[BATCH * NPTS * KNN];     // knn indices
__device__ float g_U  [BATCH * NPTS * 512];     // W_left  @ x
__device__ float g_V  [BATCH * NPTS * 512];     // W_right @ x
__device__ float g_H  [BATCH * NPTS * HDIM];    // concat(x1,x2,x3,x4)
__device__ float g_H5 [BATCH * NPTS * 1024];    // conv5 output
__device__ float g_pmax[BATCH * PCH * 1024];
__device__ float g_psum[BATCH * PCH * 1024];
__device__ float g_pool[BATCH * 2048];
__device__ float g_z   [BATCH * 512];

// ---------------------------------------------------------------------------
// Transpose: x (B, C, N) -> XT (B, N, C)
// ---------------------------------------------------------------------------
__global__ void transpose_kernel(const float* __restrict__ x, float* __restrict__ xt) {
    __shared__ float tile[32][33];
    int b  = blockIdx.z;
    int c0 = blockIdx.y * 32;
    int n0 = blockIdx.x * 32;
    const float* xb  = x  + (long)b * CIN * NPTS;
    float*       xtb = xt + (long)b * NPTS * CIN;
    int tx = threadIdx.x, ty = threadIdx.y;            // 32 x 8
#pragma unroll
    for (int i = 0; i < 32; i += 8)
        tile[ty + i][tx] = xb[(long)(c0 + ty + i) * NPTS + n0 + tx];
    __syncthreads();
#pragma unroll
    for (int i = 0; i < 32; i += 8)
        xtb[(long)(n0 + ty + i) * CIN + c0 + tx] = tile[tx][ty + i];
}

// ---------------------------------------------------------------------------
// Generic tiled SGEMM:  C[b](M x N) = A[b](M x K, lda) * B[b](N x K, ldb)^T
// Optional epilogue: batchnorm(scale/shift per out-channel) + leaky_relu(0.2)
// Requirements: M % 64 == 0, N % 64 == 0, K % 16 == 0, all float4 bases aligned
// ---------------------------------------------------------------------------
#define BM 64
#define BN 64
#define BK 16

__global__ void __launch_bounds__(256)
gemm_nt(const float* __restrict__ A, int lda, long strideA,
        const float* __restrict__ Bm, int ldb, long strideB,
        float* __restrict__ C, int ldc, long strideC,
        int M, int Nn, int K,
        const float* __restrict__ bn, int bnN)
{
    __shared__ __align__(16) float As[BK][BM];
    __shared__ __align__(16) float Bs[BK][BN];

    int bz = blockIdx.z;
    const float* Ab = A  + (long)bz * strideA;
    const float* Bb = Bm + (long)bz * strideB;
    float*       Cb = C  + (long)bz * strideC;

    int m0 = blockIdx.y * BM;
    int n0 = blockIdx.x * BN;
    int tid = threadIdx.x;

    int lrow = tid >> 2;            // 0..63
    int lk4  = (tid & 3) * 4;       // 0,4,8,12
    int tx = tid & 15, ty = tid >> 4;

    float acc[4][4] = {};

    for (int k0 = 0; k0 < K; k0 += BK) {
        float4 av = *reinterpret_cast<const float4*>(&Ab[(long)(m0 + lrow) * lda + k0 + lk4]);
        float4 bv = *reinterpret_cast<const float4*>(&Bb[(long)(n0 + lrow) * ldb + k0 + lk4]);
        As[lk4 + 0][lrow] = av.x; As[lk4 + 1][lrow] = av.y;
        As[lk4 + 2][lrow] = av.z; As[lk4 + 3][lrow] = av.w;
        Bs[lk4 + 0][lrow] = bv.x; Bs[lk4 + 1][lrow] = bv.y;
        Bs[lk4 + 2][lrow] = bv.z; Bs[lk4 + 3][lrow] = bv.w;
        __syncthreads();

#pragma unroll
        for (int k = 0; k < BK; k++) {
            float4 a0 = *reinterpret_cast<const float4*>(&As[k][ty * 4]);
            float4 b0 = *reinterpret_cast<const float4*>(&Bs[k][tx * 4]);
            acc[0][0] += a0.x * b0.x; acc[0][1] += a0.x * b0.y;
            acc[0][2] += a0.x * b0.z; acc[0][3] += a0.x * b0.w;
            acc[1][0] += a0.y * b0.x; acc[1][1] += a0.y * b0.y;
            acc[1][2] += a0.y * b0.z; acc[1][3] += a0.y * b0.w;
            acc[2][0] += a0.z * b0.x; acc[2][1] += a0.z * b0.y;
            acc[2][2] += a0.z * b0.z; acc[2][3] += a0.z * b0.w;
            acc[3][0] += a0.w * b0.x; acc[3][1] += a0.w * b0.y;
            acc[3][2] += a0.w * b0.z; acc[3][3] += a0.w * b0.w;
        }
        __syncthreads();
    }

#pragma unroll
    for (int i = 0; i < 4; i++) {
#pragma unroll
        for (int j = 0; j < 4; j++) {
            int m = m0 + ty * 4 + i;
            int n = n0 + tx * 4 + j;
            float val = acc[i][j];
            if (bn) {
                float gg = bn[n], bb = bn[bnN + n], mm = bn[2 * bnN + n], vv = bn[3 * bnN + n];
                float s = gg * rsqrtf(vv + EPS);
                val = (val - mm) * s + bb;
                val = val > 0.f ? val : 0.2f * val;
            }
            Cb[(long)m * ldc + n] = val;
        }
    }
}

// ---------------------------------------------------------------------------
// Top-K (K=20) per row of the Gram matrix.
// ordering key: 2*G[n][m] - G[m][m]   (constant -||x_n||^2 dropped)
// tie-break: lower index (matches jax.lax.top_k)
// ---------------------------------------------------------------------------
__global__ void __launch_bounds__(256)
topk_kernel(const float* __restrict__ G, int* __restrict__ idx)
{
    int b = blockIdx.y;
    int n = blockIdx.x;
    const float* Gb = G + ((long)b * NPTS + n) * NPTS;
    const float* Gd = G + (long)b * NPTS * NPTS;

    __shared__ float key[NPTS];
    __shared__ float rv[256];
    __shared__ int   ri[256];
    int tid = threadIdx.x;

    for (int m = tid; m < NPTS; m += 256)
        key[m] = 2.f * Gb[m] - Gd[(long)m * NPTS + m];
    __syncthreads();

    for (int it = 0; it < KNN; ++it) {
        float bestv = -CUDART_INF_F;
        int   besti = 0;
        for (int m = tid; m < NPTS; m += 256) {
            float v = key[m];
            if (v > bestv) { bestv = v; besti = m; }
        }
        rv[tid] = bestv; ri[tid] = besti;
        __syncthreads();
        for (int s = 128; s > 0; s >>= 1) {
            if (tid < s) {
                float v = rv[tid + s]; int i2 = ri[tid + s];
                if (v > rv[tid] || (v == rv[tid] && i2 < ri[tid])) { rv[tid] = v; ri[tid] = i2; }
            }
            __syncthreads();
        }
        if (tid == 0) {
            idx[((long)b * NPTS + n) * KNN + it] = ri[0];
            key[ri[0]] = -CUDART_INF_F;
        }
        __syncthreads();
    }
}

// ---------------------------------------------------------------------------
// EdgeConv aggregation:
// out[n][o] = bn_lrelu( max_k U[idx[n,k]][o]  -  U[n][o] + V[n][o] )
// (valid because bn scale > 0 and leaky_relu are monotone increasing)
// ---------------------------------------------------------------------------
__global__ void __launch_bounds__(256)
aggregate_kernel(const float* __restrict__ U, const float* __restrict__ V,
                 const int* __restrict__ idx, const float* __restrict__ bn,
                 float* __restrict__ out, int O, int ldo)
{
    int b = blockIdx.y, n = blockIdx.x;
    __shared__ int nb[KNN];
    int tid = threadIdx.x;
    if (tid < KNN) nb[tid] = idx[((long)b * NPTS + n) * KNN + tid];
    __syncthreads();

    const float* Ub = U + (long)b * NPTS * O;
    const float* un = Ub + (long)n * O;
    const float* vn = V + ((long)b * NPTS + n) * O;
    float*       on = out + ((long)b * NPTS + n) * ldo;

    for (int o = tid; o < O; o += 256) {
        float mx = -CUDART_INF_F;
#pragma unroll
        for (int k = 0; k < KNN; k++)
            mx = fmaxf(mx, Ub[(long)nb[k] * O + o]);
        float y = mx - un[o] + vn[o];
        float g = bn[o], be = bn[O + o], mm = bn[2 * O + o], vv = bn[3 * O + o];
        float s = g * rsqrtf(vv + EPS);
        y = (y - mm) * s + be;
        on[o] = y > 0.f ? y : 0.2f * y;
    }
}

// ---------------------------------------------------------------------------
// Pooling (max + mean over N), two-stage
// ---------------------------------------------------------------------------
__global__ void __launch_bounds__(256)
pool1_kernel(const float* __restrict__ H5, float* __restrict__ pmax, float* __restrict__ psum)
{
    int b = blockIdx.y, chunk = blockIdx.x;      // PCH chunks of 32 rows
    int tid = threadIdx.x;
    float mx[4] = {-CUDART_INF_F, -CUDART_INF_F, -CUDART_INF_F, -CUDART_INF_F};
    float sm[4] = {0.f, 0.f, 0.f, 0.f};
    const float* h = H5 + ((long)b * NPTS + chunk * 32) * 1024;
    for (int n = 0; n < 32; n++) {
        const float* row = h + (long)n * 1024;
#pragma unroll
        for (int q = 0; q < 4; q++) {
            float v = row[tid + 256 * q];
            mx[q] = fmaxf(mx[q], v);
            sm[q] += v;
        }
    }
#pragma unroll
    for (int q = 0; q < 4; q++) {
        int o = tid + 256 * q;
        pmax[((long)b * PCH + chunk) * 1024 + o] = mx[q];
        psum[((long)b * PCH + chunk) * 1024 + o] = sm[q];
    }
}

__global__ void __launch_bounds__(256)
pool2_kernel(const float* __restrict__ pmax, const float* __restrict__ psum,
             float* __restrict__ pooled)
{
    int b = blockIdx.y;
    int o = blockIdx.x * 256 + threadIdx.x;      // 0..1023
    float mx = -CUDART_INF_F, sm = 0.f;
    for (int c = 0; c < PCH; c++) {
        mx = fmaxf(mx, pmax[((long)b * PCH + c) * 1024 + o]);
        sm += psum[((long)b * PCH + c) * 1024 + o];
    }
    pooled[b * 2048 + o]        = mx;
    pooled[b * 2048 + 1024 + o] = sm * (1.f / NPTS);
}

// ---------------------------------------------------------------------------
// Head:  z = bn_lrelu(pooled @ Wl1^T);  out = z @ Wl3^T + bl3
// ---------------------------------------------------------------------------
__global__ void __launch_bounds__(256)
head1_kernel(const float* __restrict__ pooled, const float* __restrict__ Wl1,
             const float* __restrict__ bn6, float* __restrict__ z)
{
    int b = blockIdx.y, j = blockIdx.x;          // j < 512
    int tid = threadIdx.x;
    const float* p = pooled + b * 2048;
    const float* w = Wl1 + (long)j * 2048;
    float s = 0.f;
    for (int c = tid; c < 2048; c += 256) s += p[c] * w[c];
    __shared__ float red[256];
    red[tid] = s; __syncthreads();
    for (int st = 128; st > 0; st >>= 1) {
        if (tid < st) red[tid] += red[tid + st];
        __syncthreads();
    }
    if (tid == 0) {
        float y = red[0];
        float g = bn6[j], be = bn6[512 + j], mm = bn6[1024 + j], vv = bn6[1536 + j];
        y = (y - mm) * (g * rsqrtf(vv + EPS)) + be;
        z[b * 512 + j] = y > 0.f ? y : 0.2f * y;
    }
}

__global__ void __launch_bounds__(128)
head2_kernel(const float* __restrict__ z, const float* __restrict__ Wl3,
             const float* __restrict__ bl3, float* __restrict__ out)
{
    int b = blockIdx.y, t = blockIdx.x;          // t < 40
    int tid = threadIdx.x;
    const float* zb = z + b * 512;
    const float* w  = Wl3 + (long)t * 512;
    float s = 0.f;
    for (int c = tid; c < 512; c += 128) s += zb[c] * w[c];
    __shared__ float red[128];
    red[tid] = s; __syncthreads();
    for (int st = 64; st > 0; st >>= 1) {
        if (tid < st) red[tid] += red[tid + st];
        __syncthreads();
    }
    if (tid == 0) out[b * 40 + t] = red[0] + bl3[t];
}

// ---------------------------------------------------------------------------
// Host driver
// ---------------------------------------------------------------------------
static void launch_gemm(const float* A, int lda, long sA,
                        const float* Bm, int ldb, long sB,
                        float* C, int ldc, long sC,
                        int M, int N, int K,
                        const float* bn, int bnN)
{
    dim3 grid(N / BN, M / BM, BATCH);
    gemm_nt<<<grid, 256>>>(A, lda, sA, Bm, ldb, sB, C, ldc, sC, M, N, K, bn, bnN);
}

static void run_edgeconv(const float* Xin, int lda, int Kdim,
                         const float* W, const float* bn, int O,
                         float* Hout, int ldo,
                         float* G, int* idx, float* U, float* V)
{
    // 1) Gram matrix
    launch_gemm(Xin, lda, (long)NPTS * lda, Xin, lda, (long)NPTS * lda,
                G, NPTS, (long)NPTS * NPTS, NPTS, NPTS, Kdim, nullptr, 0);
    // 2) top-20 per row
    topk_kernel<<<dim3(NPTS, BATCH), 256>>>(G, idx);
    // 3) U = X @ W_left^T,  V = X @ W_right^T
    launch_gemm(Xin, lda, (long)NPTS * lda, W,        2 * Kdim, 0,
                U, O, (long)NPTS * O, NPTS, O, Kdim, nullptr, 0);
    launch_gemm(Xin, lda, (long)NPTS * lda, W + Kdim, 2 * Kdim, 0,
                V, O, (long)NPTS * O, NPTS, O, Kdim, nullptr, 0);
    // 4) gather + max + bn + lrelu
    aggregate_kernel<<<dim3(NPTS, BATCH), 256>>>(U, V, idx, bn, Hout, O, ldo);
}

extern "C" void kernel_launch(void* const* d_in, const int* in_sizes, int n_in,
                              void* d_out, int out_size)
{
    (void)in_sizes; (void)n_in; (void)out_size;
    const float* x   = (const float*)d_in[0];
    const float* W1  = (const float*)d_in[1];
    const float* bn1 = (const float*)d_in[2];
    const float* W2  = (const float*)d_in[3];
    const float* bn2 = (const float*)d_in[4];
    const float* W3  = (const float*)d_in[5];
    const float* bn3 = (const float*)d_in[6];
    const float* W4  = (const float*)d_in[7];
    const float* bn4 = (const float*)d_in[8];
    const float* W5  = (const float*)d_in[9];
    const float* bn5 = (const float*)d_in[10];
    const float* Wl1 = (const float*)d_in[11];
    const float* bn6 = (const float*)d_in[12];
    const float* Wl3 = (const float*)d_in[13];
    const float* bl3 = (const float*)d_in[14];
    float* out = (float*)d_out;

    float *XT, *G, *U, *V, *H, *H5, *pmax, *psum, *pool, *z;
    int* idx;
    cudaGetSymbolAddress((void**)&XT,   g_XT);
    cudaGetSymbolAddress((void**)&G,    g_G);
    cudaGetSymbolAddress((void**)&idx,  g_idx);
    cudaGetSymbolAddress((void**)&U,    g_U);
    cudaGetSymbolAddress((void**)&V,    g_V);
    cudaGetSymbolAddress((void**)&H,    g_H);
    cudaGetSymbolAddress((void**)&H5,   g_H5);
    cudaGetSymbolAddress((void**)&pmax, g_pmax);
    cudaGetSymbolAddress((void**)&psum, g_psum);
    cudaGetSymbolAddress((void**)&pool, g_pool);
    cudaGetSymbolAddress((void**)&z,    g_z);

    // transpose x (B,C,N) -> XT (B,N,C)
    transpose_kernel<<<dim3(NPTS / 32, CIN / 32, BATCH), dim3(32, 8)>>>(x, XT);

    // EdgeConv 1..4, outputs written into slices of H (ld = 1152)
    run_edgeconv(XT,      CIN,  768, W1, bn1, 512, H,       HDIM, G, idx, U, V);
    run_edgeconv(H,       HDIM, 512, W2, bn2, 256, H + 512, HDIM, G, idx, U, V);
    run_edgeconv(H + 512, HDIM, 256, W3, bn3, 128, H + 768, HDIM, G, idx, U, V);
    run_edgeconv(H + 768, HDIM, 128, W4, bn4, 256, H + 896, HDIM, G, idx, U, V);

    // conv5: H (N x 1152) @ W5^T (1152 x 1024) + bn5 + lrelu  -> H5
    launch_gemm(H, HDIM, (long)NPTS * HDIM, W5, HDIM, 0,
                H5, 1024, (long)NPTS * 1024, NPTS, 1024, HDIM, bn5, 1024);

    // pooling -> pooled (B x 2048)
    pool1_kernel<<<dim3(PCH, BATCH), 256>>>(H5, pmax, psum);
    pool2_kernel<<<dim3(4, BATCH), 256>>>(pmax, psum, pool);

    // head
    head1_kernel<<<dim3(512, BATCH), 256>>>(pool, Wl1, bn6, z);
    head2_kernel<<<dim3(40, BATCH), 128>>>(z, Wl3, bl3, out);
}

// round 3
// speedup vs baseline: 1.1768x; 1.1768x over previous
#include <cuda_runtime.h>
#include <math_constants.h>

// ---------------------------------------------------------------------------
// Problem constants
// ---------------------------------------------------------------------------
#define BATCH 4
#define NPTS  1024
#define CIN   768
#define KNN   20
#define HDIM  1152    // 512 + 256 + 128 + 256
#define PCH   32      // pooling chunks
#define EPS   1e-5f

// ---------------------------------------------------------------------------
// Scratch (device globals; no allocation allowed)
// ---------------------------------------------------------------------------
__device__ float g_XT [BATCH * NPTS * CIN];     // x transposed: (B, N, C)
__device__ float g_G  [BATCH * NPTS * NPTS];    // gram matrix
__device__ int   g_idx[BATCH * NPTS * KNN];     // knn indices
__device__ float g_U  [BATCH * NPTS * 512];     // W_left  @ x
__device__ float g_V  [BATCH * NPTS * 512];     // W_right @ x
__device__ float g_H  [BATCH * NPTS * HDIM];    // concat(x1,x2,x3,x4)
__device__ float g_H5 [BATCH * NPTS * 1024];    // conv5 output
__device__ float g_pmax[BATCH * PCH * 1024];
__device__ float g_psum[BATCH * PCH * 1024];
__device__ float g_pool[BATCH * 2048];
__device__ float g_z   [BATCH * 512];

// ---------------------------------------------------------------------------
// Transpose: x (B, C, N) -> XT (B, N, C)
// ---------------------------------------------------------------------------
__global__ void transpose_kernel(const float* __restrict__ x, float* __restrict__ xt) {
    __shared__ float tile[32][33];
    int b  = blockIdx.z;
    int c0 = blockIdx.y * 32;
    int n0 = blockIdx.x * 32;
    const float* xb  = x  + (long)b * CIN * NPTS;
    float*       xtb = xt + (long)b * NPTS * CIN;
    int tx = threadIdx.x, ty = threadIdx.y;            // 32 x 8
#pragma unroll
    for (int i = 0; i < 32; i += 8)
        tile[ty + i][tx] = xb[(long)(c0 + ty + i) * NPTS + n0 + tx];
    __syncthreads();
#pragma unroll
    for (int i = 0; i < 32; i += 8)
        xtb[(long)(n0 + ty + i) * CIN + c0 + tx] = tile[tx][ty + i];
}

// ---------------------------------------------------------------------------
// Tiled SGEMM:  C[b](M x N) = A[b](M x K, lda) * B[b](N x K, ldb)^T
// 128x128x16 tiles, 8x8 per-thread register blocking, double-buffered smem.
// Accumulation order over k is sequential (identical numerics to previous
// version -> KNN indices unchanged).
// Optional epilogue: batchnorm + leaky_relu(0.2).
// Requirements: M % 128 == 0, N % 128 == 0, K % 16 == 0
// ---------------------------------------------------------------------------
#define BM 128
#define BN 128
#define BK 16

__global__ void __launch_bounds__(256, 2)
gemm_nt(const float* __restrict__ A, int lda, long strideA,
        const float* __restrict__ Bm, int ldb, long strideB,
        float* __restrict__ C, int ldc, long strideC,
        int M, int Nn, int K,
        const float* __restrict__ bn, int bnN)
{
    __shared__ __align__(16) float As[2][BK][BM];
    __shared__ __align__(16) float Bs[2][BK][BN];

    const int bz = blockIdx.z;
    const float* Ab = A  + (long)bz * strideA;
    const float* Bb = Bm + (long)bz * strideB;
    float*       Cb = C  + (long)bz * strideC;

    const int m0 = blockIdx.y * BM;
    const int n0 = blockIdx.x * BN;
    const int tid = threadIdx.x;

    // loader mapping: each thread loads rows lr and lr+64, 4 k-values each
    const int lr = tid >> 2;            // 0..63
    const int lc = (tid & 3) * 4;       // 0,4,8,12

    // compute mapping: 16x16 thread grid, 8x8 outputs each
    const int ty = tid >> 4;            // 0..15
    const int tx = tid & 15;            // 0..15

    float acc[8][8];
#pragma unroll
    for (int i = 0; i < 8; i++)
#pragma unroll
        for (int j = 0; j < 8; j++) acc[i][j] = 0.f;

    const int nTiles = K / BK;
    float4 pa0, pa1, pb0, pb1;

    // prefetch tile 0
    pa0 = *reinterpret_cast<const float4*>(&Ab[(long)(m0 + lr)      * lda + lc]);
    pa1 = *reinterpret_cast<const float4*>(&Ab[(long)(m0 + lr + 64) * lda + lc]);
    pb0 = *reinterpret_cast<const float4*>(&Bb[(long)(n0 + lr)      * ldb + lc]);
    pb1 = *reinterpret_cast<const float4*>(&Bb[(long)(n0 + lr + 64) * ldb + lc]);
    {
        As[0][lc + 0][lr] = pa0.x; As[0][lc + 1][lr] = pa0.y;
        As[0][lc + 2][lr] = pa0.z; As[0][lc + 3][lr] = pa0.w;
        As[0][lc + 0][lr + 64] = pa1.x; As[0][lc + 1][lr + 64] = pa1.y;
        As[0][lc + 2][lr + 64] = pa1.z; As[0][lc + 3][lr + 64] = pa1.w;
        Bs[0][lc + 0][lr] = pb0.x; Bs[0][lc + 1][lr] = pb0.y;
        Bs[0][lc + 2][lr] = pb0.z; Bs[0][lc + 3][lr] = pb0.w;
        Bs[0][lc + 0][lr + 64] = pb1.x; Bs[0][lc + 1][lr + 64] = pb1.y;
        Bs[0][lc + 2][lr + 64] = pb1.z; Bs[0][lc + 3][lr + 64] = pb1.w;
    }
    __syncthreads();

    for (int t = 0; t < nTiles; t++) {
        const int cur = t & 1;
        // prefetch next tile (global -> regs) before compute
        if (t + 1 < nTiles) {
            const int k0 = (t + 1) * BK;
            pa0 = *reinterpret_cast<const float4*>(&Ab[(long)(m0 + lr)      * lda + k0 + lc]);
            pa1 = *reinterpret_cast<const float4*>(&Ab[(long)(m0 + lr + 64) * lda + k0 + lc]);
            pb0 = *reinterpret_cast<const float4*>(&Bb[(long)(n0 + lr)      * ldb + k0 + lc]);
            pb1 = *reinterpret_cast<const float4*>(&Bb[(long)(n0 + lr + 64) * ldb + k0 + lc]);
        }

#pragma unroll
        for (int k = 0; k < BK; k++) {
            float4 a0 = *reinterpret_cast<const float4*>(&As[cur][k][ty * 8]);
            float4 a1 = *reinterpret_cast<const float4*>(&As[cur][k][ty * 8 + 4]);
            float4 b0 = *reinterpret_cast<const float4*>(&Bs[cur][k][tx * 8]);
            float4 b1 = *reinterpret_cast<const float4*>(&Bs[cur][k][tx * 8 + 4]);
            float av[8] = {a0.x, a0.y, a0.z, a0.w, a1.x, a1.y, a1.z, a1.w};
            float bv[8] = {b0.x, b0.y, b0.z, b0.w, b1.x, b1.y, b1.z, b1.w};
#pragma unroll
            for (int i = 0; i < 8; i++)
#pragma unroll
                for (int j = 0; j < 8; j++)
                    acc[i][j] += av[i] * bv[j];
        }

        if (t + 1 < nTiles) {
            const int nxt = 1 - cur;
            As[nxt][lc + 0][lr] = pa0.x; As[nxt][lc + 1][lr] = pa0.y;
            As[nxt][lc + 2][lr] = pa0.z; As[nxt][lc + 3][lr] = pa0.w;
            As[nxt][lc + 0][lr + 64] = pa1.x; As[nxt][lc + 1][lr + 64] = pa1.y;
            As[nxt][lc + 2][lr + 64] = pa1.z; As[nxt][lc + 3][lr + 64] = pa1.w;
            Bs[nxt][lc + 0][lr] = pb0.x; Bs[nxt][lc + 1][lr] = pb0.y;
            Bs[nxt][lc + 2][lr] = pb0.z; Bs[nxt][lc + 3][lr] = pb0.w;
            Bs[nxt][lc + 0][lr + 64] = pb1.x; Bs[nxt][lc + 1][lr + 64] = pb1.y;
            Bs[nxt][lc + 2][lr + 64] = pb1.z; Bs[nxt][lc + 3][lr + 64] = pb1.w;
        }
        __syncthreads();
    }

    // epilogue
    const int cm = m0 + ty * 8;
    const int cn = n0 + tx * 8;
    if (bn) {
        float sc[8], sh[8];
#pragma unroll
        for (int j = 0; j < 8; j++) {
            int n = cn + j;
            float g = bn[n], b = bn[bnN + n], m = bn[2 * bnN + n], v = bn[3 * bnN + n];
            sc[j] = g * rsqrtf(v + EPS);
            sh[j] = b - m * sc[j];
        }
#pragma unroll
        for (int i = 0; i < 8; i++) {
#pragma unroll
            for (int j = 0; j < 8; j++) {
                float val = acc[i][j] * sc[j] + sh[j];
                acc[i][j] = val > 0.f ? val : 0.2f * val;
            }
        }
    }
#pragma unroll
    for (int i = 0; i < 8; i++) {
        float4 v0 = make_float4(acc[i][0], acc[i][1], acc[i][2], acc[i][3]);
        float4 v1 = make_float4(acc[i][4], acc[i][5], acc[i][6], acc[i][7]);
        *reinterpret_cast<float4*>(&Cb[(long)(cm + i) * ldc + cn])     = v0;
        *reinterpret_cast<float4*>(&Cb[(long)(cm + i) * ldc + cn + 4]) = v1;
    }
}

// ---------------------------------------------------------------------------
// Top-K (K=20) per row of the Gram matrix, warp-shuffle reductions.
// ordering key: 2*G[n][m] - G[m][m]   (constant -||x_n||^2 dropped)
// tie-break: lower index (matches jax.lax.top_k)
// ---------------------------------------------------------------------------
__global__ void __launch_bounds__(256)
topk_kernel(const float* __restrict__ G, int* __restrict__ idx)
{
    int b = blockIdx.y;
    int n = blockIdx.x;
    const float* Gb = G + ((long)b * NPTS + n) * NPTS;
    const float* Gd = G + (long)b * NPTS * NPTS;

    __shared__ float key[NPTS];
    __shared__ float wv[8];
    __shared__ int   wi[8];
    int tid = threadIdx.x;
    int lane = tid & 31, wid = tid >> 5;

    for (int m = tid; m < NPTS; m += 256)
        key[m] = 2.f * Gb[m] - Gd[(long)m * NPTS + m];
    __syncthreads();

    for (int it = 0; it < KNN; ++it) {
        float bv = -CUDART_INF_F;
        int   bi = 0x7fffffff;
#pragma unroll
        for (int q = 0; q < 4; q++) {
            int m = tid + 256 * q;
            float v = key[m];
            if (v > bv) { bv = v; bi = m; }   // increasing m: strict > keeps lowest idx
        }
#pragma unroll
        for (int off = 16; off > 0; off >>= 1) {
            float ov = __shfl_down_sync(0xffffffffu, bv, off);
            int   oi = __shfl_down_sync(0xffffffffu, bi, off);
            if (ov > bv || (ov == bv && oi < bi)) { bv = ov; bi = oi; }
        }
        if (lane == 0) { wv[wid] = bv; wi[wid] = bi; }
        __syncthreads();
        if (wid == 0) {
            bv = (lane < 8) ? wv[lane] : -CUDART_INF_F;
            bi = (lane < 8) ? wi[lane] : 0x7fffffff;
#pragma unroll
            for (int off = 4; off > 0; off >>= 1) {
                float ov = __shfl_down_sync(0xffffffffu, bv, off);
                int   oi = __shfl_down_sync(0xffffffffu, bi, off);
                if (ov > bv || (ov == bv && oi < bi)) { bv = ov; bi = oi; }
            }
            if (lane == 0) {
                idx[((long)b * NPTS + n) * KNN + it] = bi;
                key[bi] = -CUDART_INF_F;
            }
        }
        __syncthreads();
    }
}

// ---------------------------------------------------------------------------
// EdgeConv aggregation:
// out[n][o] = bn_lrelu( max_k U[idx[n,k]][o]  -  U[n][o] + V[n][o] )
// (valid because bn scale > 0 and leaky_relu are monotone increasing)
// ---------------------------------------------------------------------------
__global__ void __launch_bounds__(256)
aggregate_kernel(const float* __restrict__ U, const float* __restrict__ V,
                 const int* __restrict__ idx, const float* __restrict__ bn,
                 float* __restrict__ out, int O, int ldo)
{
    int b = blockIdx.y, n = blockIdx.x;
    __shared__ int nb[KNN];
    int tid = threadIdx.x;
    if (tid < KNN) nb[tid] = idx[((long)b * NPTS + n) * KNN + tid];
    __syncthreads();

    const float* Ub = U + (long)b * NPTS * O;
    const float* un = Ub + (long)n * O;
    const float* vn = V + ((long)b * NPTS + n) * O;
    float*       on = out + ((long)b * NPTS + n) * ldo;

    for (int o = tid; o < O; o += 256) {
        float mx = -CUDART_INF_F;
#pragma unroll
        for (int k = 0; k < KNN; k++)
            mx = fmaxf(mx, Ub[(long)nb[k] * O + o]);
        float y = mx - un[o] + vn[o];
        float g = bn[o], be = bn[O + o], mm = bn[2 * O + o], vv = bn[3 * O + o];
        float s = g * rsqrtf(vv + EPS);
        y = (y - mm) * s + be;
        on[o] = y > 0.f ? y : 0.2f * y;
    }
}

// ---------------------------------------------------------------------------
// Pooling (max + mean over N), two-stage
// ---------------------------------------------------------------------------
__global__ void __launch_bounds__(256)
pool1_kernel(const float* __restrict__ H5, float* __restrict__ pmax, float* __restrict__ psum)
{
    int b = blockIdx.y, chunk = blockIdx.x;      // PCH chunks of 32 rows
    int tid = threadIdx.x;
    float mx[4] = {-CUDART_INF_F, -CUDART_INF_F, -CUDART_INF_F, -CUDART_INF_F};
    float sm[4] = {0.f, 0.f, 0.f, 0.f};
    const float* h = H5 + ((long)b * NPTS + chunk * 32) * 1024;
    for (int n = 0; n < 32; n++) {
        const float* row = h + (long)n * 1024;
#pragma unroll
        for (int q = 0; q < 4; q++) {
            float v = row[tid + 256 * q];
            mx[q] = fmaxf(mx[q], v);
            sm[q] += v;
        }
    }
#pragma unroll
    for (int q = 0; q < 4; q++) {
        int o = tid + 256 * q;
        pmax[((long)b * PCH + chunk) * 1024 + o] = mx[q];
        psum[((long)b * PCH + chunk) * 1024 + o] = sm[q];
    }
}

__global__ void __launch_bounds__(256)
pool2_kernel(const float* __restrict__ pmax, const float* __restrict__ psum,
             float* __restrict__ pooled)
{
    int b = blockIdx.y;
    int o = blockIdx.x * 256 + threadIdx.x;      // 0..1023
    float mx = -CUDART_INF_F, sm = 0.f;
    for (int c = 0; c < PCH; c++) {
        mx = fmaxf(mx, pmax[((long)b * PCH + c) * 1024 + o]);
        sm += psum[((long)b * PCH + c) * 1024 + o];
    }
    pooled[b * 2048 + o]        = mx;
    pooled[b * 2048 + 1024 + o] = sm * (1.f / NPTS);
}

// ---------------------------------------------------------------------------
// Head:  z = bn_lrelu(pooled @ Wl1^T);  out = z @ Wl3^T + bl3
// ---------------------------------------------------------------------------
__global__ void __launch_bounds__(256)
head1_kernel(const float* __restrict__ pooled, const float* __restrict__ Wl1,
             const float* __restrict__ bn6, float* __restrict__ z)
{
    int b = blockIdx.y, j = blockIdx.x;          // j < 512
    int tid = threadIdx.x;
    const float* p = pooled + b * 2048;
    const float* w = Wl1 + (long)j * 2048;
    float s = 0.f;
    for (int c = tid; c < 2048; c += 256) s += p[c] * w[c];
    __shared__ float red[256];
    red[tid] = s; __syncthreads();
    for (int st = 128; st > 0; st >>= 1) {
        if (tid < st) red[tid] += red[tid + st];
        __syncthreads();
    }
    if (tid == 0) {
        float y = red[0];
        float g = bn6[j], be = bn6[512 + j], mm = bn6[1024 + j], vv = bn6[1536 + j];
        y = (y - mm) * (g * rsqrtf(vv + EPS)) + be;
        z[b * 512 + j] = y > 0.f ? y : 0.2f * y;
    }
}

__global__ void __launch_bounds__(128)
head2_kernel(const float* __restrict__ z, const float* __restrict__ Wl3,
             const float* __restrict__ bl3, float* __restrict__ out)
{
    int b = blockIdx.y, t = blockIdx.x;          // t < 40
    int tid = threadIdx.x;
    const float* zb = z + b * 512;
    const float* w  = Wl3 + (long)t * 512;
    float s = 0.f;
    for (int c = tid; c < 512; c += 128) s += zb[c] * w[c];
    __shared__ float red[128];
    red[tid] = s; __syncthreads();
    for (int st = 64; st > 0; st >>= 1) {
        if (tid < st) red[tid] += red[tid + st];
        __syncthreads();
    }
    if (tid == 0) out[b * 40 + t] = red[0] + bl3[t];
}

// ---------------------------------------------------------------------------
// Host driver
// ---------------------------------------------------------------------------
static void launch_gemm(const float* A, int lda, long sA,
                        const float* Bm, int ldb, long sB,
                        float* C, int ldc, long sC,
                        int M, int N, int K,
                        const float* bn, int bnN)
{
    dim3 grid(N / BN, M / BM, BATCH);
    gemm_nt<<<grid, 256>>>(A, lda, sA, Bm, ldb, sB, C, ldc, sC, M, N, K, bn, bnN);
}

static void run_edgeconv(const float* Xin, int lda, int Kdim,
                         const float* W, const float* bn, int O,
                         float* Hout, int ldo,
                         float* G, int* idx, float* U, float* V)
{
    // 1) Gram matrix
    launch_gemm(Xin, lda, (long)NPTS * lda, Xin, lda, (long)NPTS * lda,
                G, NPTS, (long)NPTS * NPTS, NPTS, NPTS, Kdim, nullptr, 0);
    // 2) top-20 per row
    topk_kernel<<<dim3(NPTS, BATCH), 256>>>(G, idx);
    // 3) U = X @ W_left^T,  V = X @ W_right^T
    launch_gemm(Xin, lda, (long)NPTS * lda, W,        2 * Kdim, 0,
                U, O, (long)NPTS * O, NPTS, O, Kdim, nullptr, 0);
    launch_gemm(Xin, lda, (long)NPTS * lda, W + Kdim, 2 * Kdim, 0,
                V, O, (long)NPTS * O, NPTS, O, Kdim, nullptr, 0);
    // 4) gather + max + bn + lrelu
    aggregate_kernel<<<dim3(NPTS, BATCH), 256>>>(U, V, idx, bn, Hout, O, ldo);
}

extern "C" void kernel_launch(void* const* d_in, const int* in_sizes, int n_in,
                              void* d_out, int out_size)
{
    (void)in_sizes; (void)n_in; (void)out_size;
    const float* x   = (const float*)d_in[0];
    const float* W1  = (const float*)d_in[1];
    const float* bn1 = (const float*)d_in[2];
    const float* W2  = (const float*)d_in[3];
    const float* bn2 = (const float*)d_in[4];
    const float* W3  = (const float*)d_in[5];
    const float* bn3 = (const float*)d_in[6];
    const float* W4  = (const float*)d_in[7];
    const float* bn4 = (const float*)d_in[8];
    const float* W5  = (const float*)d_in[9];
    const float* bn5 = (const float*)d_in[10];
    const float* Wl1 = (const float*)d_in[11];
    const float* bn6 = (const float*)d_in[12];
    const float* Wl3 = (const float*)d_in[13];
    const float* bl3 = (const float*)d_in[14];
    float* out = (float*)d_out;

    float *XT, *G, *U, *V, *H, *H5, *pmax, *psum, *pool, *z;
    int* idx;
    cudaGetSymbolAddress((void**)&XT,   g_XT);
    cudaGetSymbolAddress((void**)&G,    g_G);
    cudaGetSymbolAddress((void**)&idx,  g_idx);
    cudaGetSymbolAddress((void**)&U,    g_U);
    cudaGetSymbolAddress((void**)&V,    g_V);
    cudaGetSymbolAddress((void**)&H,    g_H);
    cudaGetSymbolAddress((void**)&H5,   g_H5);
    cudaGetSymbolAddress((void**)&pmax, g_pmax);
    cudaGetSymbolAddress((void**)&psum, g_psum);
    cudaGetSymbolAddress((void**)&pool, g_pool);
    cudaGetSymbolAddress((void**)&z,    g_z);

    // transpose x (B,C,N) -> XT (B,N,C)
    transpose_kernel<<<dim3(NPTS / 32, CIN / 32, BATCH), dim3(32, 8)>>>(x, XT);

    // EdgeConv 1..4, outputs written into slices of H (ld = 1152)
    run_edgeconv(XT,      CIN,  768, W1, bn1, 512, H,       HDIM, G, idx, U, V);
    run_edgeconv(H,       HDIM, 512, W2, bn2, 256, H + 512, HDIM, G, idx, U, V);
    run_edgeconv(H + 512, HDIM, 256, W3, bn3, 128, H + 768, HDIM, G, idx, U, V);
    run_edgeconv(H + 768, HDIM, 128, W4, bn4, 256, H + 896, HDIM, G, idx, U, V);

    // conv5: H (N x 1152) @ W5^T (1152 x 1024) + bn5 + lrelu  -> H5
    launch_gemm(H, HDIM, (long)NPTS * HDIM, W5, HDIM, 0,
                H5, 1024, (long)NPTS * 1024, NPTS, 1024, HDIM, bn5, 1024);

    // pooling -> pooled (B x 2048)
    pool1_kernel<<<dim3(PCH, BATCH), 256>>>(H5, pmax, psum);
    pool2_kernel<<<dim3(4, BATCH), 256>>>(pmax, psum, pool);

    // head
    head1_kernel<<<dim3(512, BATCH), 256>>>(pool, Wl1, bn6, z);
    head2_kernel<<<dim3(40, BATCH), 128>>>(z, Wl3, bl3, out);
}

// round 4
// speedup vs baseline: 1.3497x; 1.1470x over previous
#include <cuda_runtime.h>
#include <math_constants.h>

// ---------------------------------------------------------------------------
// Problem constants
// ---------------------------------------------------------------------------
#define BATCH 4
#define NPTS  1024
#define CIN   768
#define KNN   20
#define HDIM  1152    // 512 + 256 + 128 + 256
#define PCH   32      // pooling chunks
#define EPS   1e-5f

// ---------------------------------------------------------------------------
// Scratch (device globals; no allocation allowed)
// ---------------------------------------------------------------------------
__device__ float g_XT [BATCH * NPTS * CIN];     // x transposed: (B, N, C)
__device__ float g_G  [BATCH * NPTS * NPTS];    // gram matrix
__device__ int   g_idx[BATCH * NPTS * KNN];     // knn indices
__device__ float g_U  [BATCH * NPTS * 512];     // W_left  @ x
__device__ float g_V  [BATCH * NPTS * 512];     // W_right @ x
__device__ float g_H  [BATCH * NPTS * HDIM];    // concat(x1,x2,x3,x4)
__device__ float g_H5 [BATCH * NPTS * 1024];    // conv5 output
__device__ float g_pmax[BATCH * PCH * 1024];
__device__ float g_psum[BATCH * PCH * 1024];
__device__ float g_pool[BATCH * 2048];
__device__ float g_z   [BATCH * 512];

// ---------------------------------------------------------------------------
// Transpose: x (B, C, N) -> XT (B, N, C)
// ---------------------------------------------------------------------------
__global__ void transpose_kernel(const float* __restrict__ x, float* __restrict__ xt) {
    __shared__ float tile[32][33];
    int b  = blockIdx.z;
    int c0 = blockIdx.y * 32;
    int n0 = blockIdx.x * 32;
    const float* xb  = x  + (long)b * CIN * NPTS;
    float*       xtb = xt + (long)b * NPTS * CIN;
    int tx = threadIdx.x, ty = threadIdx.y;            // 32 x 8
#pragma unroll
    for (int i = 0; i < 32; i += 8)
        tile[ty + i][tx] = xb[(long)(c0 + ty + i) * NPTS + n0 + tx];
    __syncthreads();
#pragma unroll
    for (int i = 0; i < 32; i += 8)
        xtb[(long)(n0 + ty + i) * CIN + c0 + tx] = tile[tx][ty + i];
}

// ---------------------------------------------------------------------------
// Tiled SGEMM with dual-source N split:
//   blocks with n0 <  N1 compute C1 = A * B1^T
//   blocks with n0 >= N1 compute C2 = A * B2^T  (column n0-N1)
// 128x64 tiles, 8x4 per-thread register blocking, double-buffered smem,
// 256 threads, 3 CTAs/SM. Sequential k accumulation (numerics identical
// to previous passing version -> KNN indices unchanged).
// Optional epilogue: batchnorm + leaky_relu(0.2).
// Requirements: M % 128 == 0, N % 64 == 0, K % 16 == 0
// ---------------------------------------------------------------------------
#define BM 128
#define BN 64
#define BK 16

__global__ void __launch_bounds__(256, 3)
gemm_nt(const float* __restrict__ A, int lda, long strideA,
        const float* __restrict__ B1, const float* __restrict__ B2,
        int ldb, long strideB,
        float* __restrict__ C1, float* __restrict__ C2,
        int ldc, long strideC,
        int N1, int K,
        const float* __restrict__ bn, int bnN)
{
    __shared__ __align__(16) float As[2][BK][BM];
    __shared__ __align__(16) float Bs[2][BK][BN];

    const int bz = blockIdx.z;
    const int m0 = blockIdx.y * BM;
    const int nb0 = blockIdx.x * BN;

    const float* Bsel;
    float*       Csel;
    int n0;
    if (nb0 < N1) { Bsel = B1; Csel = C1; n0 = nb0; }
    else          { Bsel = B2; Csel = C2; n0 = nb0 - N1; }

    const float* Ab = A    + (long)bz * strideA;
    const float* Bb = Bsel + (long)bz * strideB;
    float*       Cb = Csel + (long)bz * strideC;

    const int tid = threadIdx.x;
    // loader mapping
    const int lr = tid >> 2;            // 0..63
    const int lc = (tid & 3) * 4;       // 0,4,8,12
    // compute mapping: 16x16 thread grid; each thread 8 rows x 4 cols
    const int ty = tid >> 4;            // 0..15
    const int tx = tid & 15;            // 0..15

    float acc[8][4];
#pragma unroll
    for (int i = 0; i < 8; i++)
#pragma unroll
        for (int j = 0; j < 4; j++) acc[i][j] = 0.f;

    const int nTiles = K / BK;
    float4 pa0, pa1, pb0;

    // prefetch tile 0
    pa0 = *reinterpret_cast<const float4*>(&Ab[(long)(m0 + lr)      * lda + lc]);
    pa1 = *reinterpret_cast<const float4*>(&Ab[(long)(m0 + lr + 64) * lda + lc]);
    pb0 = *reinterpret_cast<const float4*>(&Bb[(long)(n0 + lr)      * ldb + lc]);
    As[0][lc + 0][lr] = pa0.x; As[0][lc + 1][lr] = pa0.y;
    As[0][lc + 2][lr] = pa0.z; As[0][lc + 3][lr] = pa0.w;
    As[0][lc + 0][lr + 64] = pa1.x; As[0][lc + 1][lr + 64] = pa1.y;
    As[0][lc + 2][lr + 64] = pa1.z; As[0][lc + 3][lr + 64] = pa1.w;
    Bs[0][lc + 0][lr] = pb0.x; Bs[0][lc + 1][lr] = pb0.y;
    Bs[0][lc + 2][lr] = pb0.z; Bs[0][lc + 3][lr] = pb0.w;
    __syncthreads();

    for (int t = 0; t < nTiles; t++) {
        const int cur = t & 1;
        if (t + 1 < nTiles) {
            const int k0 = (t + 1) * BK;
            pa0 = *reinterpret_cast<const float4*>(&Ab[(long)(m0 + lr)      * lda + k0 + lc]);
            pa1 = *reinterpret_cast<const float4*>(&Ab[(long)(m0 + lr + 64) * lda + k0 + lc]);
            pb0 = *reinterpret_cast<const float4*>(&Bb[(long)(n0 + lr)      * ldb + k0 + lc]);
        }

#pragma unroll
        for (int k = 0; k < BK; k++) {
            float4 a0 = *reinterpret_cast<const float4*>(&As[cur][k][ty * 8]);
            float4 a1 = *reinterpret_cast<const float4*>(&As[cur][k][ty * 8 + 4]);
            float4 b0 = *reinterpret_cast<const float4*>(&Bs[cur][k][tx * 4]);
            float av[8] = {a0.x, a0.y, a0.z, a0.w, a1.x, a1.y, a1.z, a1.w};
            float bv[4] = {b0.x, b0.y, b0.z, b0.w};
#pragma unroll
            for (int i = 0; i < 8; i++)
#pragma unroll
                for (int j = 0; j < 4; j++)
                    acc[i][j] += av[i] * bv[j];
        }

        if (t + 1 < nTiles) {
            const int nxt = 1 - cur;
            As[nxt][lc + 0][lr] = pa0.x; As[nxt][lc + 1][lr] = pa0.y;
            As[nxt][lc + 2][lr] = pa0.z; As[nxt][lc + 3][lr] = pa0.w;
            As[nxt][lc + 0][lr + 64] = pa1.x; As[nxt][lc + 1][lr + 64] = pa1.y;
            As[nxt][lc + 2][lr + 64] = pa1.z; As[nxt][lc + 3][lr + 64] = pa1.w;
            Bs[nxt][lc + 0][lr] = pb0.x; Bs[nxt][lc + 1][lr] = pb0.y;
            Bs[nxt][lc + 2][lr] = pb0.z; Bs[nxt][lc + 3][lr] = pb0.w;
        }
        __syncthreads();
    }

    // epilogue
    const int cm = m0 + ty * 8;
    const int cn = n0 + tx * 4;
    if (bn) {
        float sc[4], sh[4];
#pragma unroll
        for (int j = 0; j < 4; j++) {
            int n = cn + j;
            float g = bn[n], b = bn[bnN + n], m = bn[2 * bnN + n], v = bn[3 * bnN + n];
            sc[j] = g * rsqrtf(v + EPS);
            sh[j] = b - m * sc[j];
        }
#pragma unroll
        for (int i = 0; i < 8; i++) {
#pragma unroll
            for (int j = 0; j < 4; j++) {
                float val = acc[i][j] * sc[j] + sh[j];
                acc[i][j] = val > 0.f ? val : 0.2f * val;
            }
        }
    }
#pragma unroll
    for (int i = 0; i < 8; i++) {
        float4 v0 = make_float4(acc[i][0], acc[i][1], acc[i][2], acc[i][3]);
        *reinterpret_cast<float4*>(&Cb[(long)(cm + i) * ldc + cn]) = v0;
    }
}

// ---------------------------------------------------------------------------
// Top-K (K=20) per row of the Gram matrix, warp-shuffle reductions.
// ordering key: 2*G[n][m] - G[m][m]   (constant -||x_n||^2 dropped)
// tie-break: lower index (matches jax.lax.top_k)
// ---------------------------------------------------------------------------
__global__ void __launch_bounds__(256)
topk_kernel(const float* __restrict__ G, int* __restrict__ idx)
{
    int b = blockIdx.y;
    int n = blockIdx.x;
    const float* Gb = G + ((long)b * NPTS + n) * NPTS;
    const float* Gd = G + (long)b * NPTS * NPTS;

    __shared__ float key[NPTS];
    __shared__ float wv[8];
    __shared__ int   wi[8];
    int tid = threadIdx.x;
    int lane = tid & 31, wid = tid >> 5;

    for (int m = tid; m < NPTS; m += 256)
        key[m] = 2.f * Gb[m] - Gd[(long)m * NPTS + m];
    __syncthreads();

    for (int it = 0; it < KNN; ++it) {
        float bv = -CUDART_INF_F;
        int   bi = 0x7fffffff;
#pragma unroll
        for (int q = 0; q < 4; q++) {
            int m = tid + 256 * q;
            float v = key[m];
            if (v > bv) { bv = v; bi = m; }   // increasing m: strict > keeps lowest idx
        }
#pragma unroll
        for (int off = 16; off > 0; off >>= 1) {
            float ov = __shfl_down_sync(0xffffffffu, bv, off);
            int   oi = __shfl_down_sync(0xffffffffu, bi, off);
            if (ov > bv || (ov == bv && oi < bi)) { bv = ov; bi = oi; }
        }
        if (lane == 0) { wv[wid] = bv; wi[wid] = bi; }
        __syncthreads();
        if (wid == 0) {
            bv = (lane < 8) ? wv[lane] : -CUDART_INF_F;
            bi = (lane < 8) ? wi[lane] : 0x7fffffff;
#pragma unroll
            for (int off = 4; off > 0; off >>= 1) {
                float ov = __shfl_down_sync(0xffffffffu, bv, off);
                int   oi = __shfl_down_sync(0xffffffffu, bi, off);
                if (ov > bv || (ov == bv && oi < bi)) { bv = ov; bi = oi; }
            }
            if (lane == 0) {
                idx[((long)b * NPTS + n) * KNN + it] = bi;
                key[bi] = -CUDART_INF_F;
            }
        }
        __syncthreads();
    }
}

// ---------------------------------------------------------------------------
// EdgeConv aggregation:
// out[n][o] = bn_lrelu( max_k U[idx[n,k]][o]  -  U[n][o] + V[n][o] )
// (valid because bn scale > 0 and leaky_relu are monotone increasing)
// ---------------------------------------------------------------------------
__global__ void __launch_bounds__(256)
aggregate_kernel(const float* __restrict__ U, const float* __restrict__ V,
                 const int* __restrict__ idx, const float* __restrict__ bn,
                 float* __restrict__ out, int O, int ldo)
{
    int b = blockIdx.y, n = blockIdx.x;
    __shared__ int nb[KNN];
    int tid = threadIdx.x;
    if (tid < KNN) nb[tid] = idx[((long)b * NPTS + n) * KNN + tid];
    __syncthreads();

    const float* Ub = U + (long)b * NPTS * O;
    const float* un = Ub + (long)n * O;
    const float* vn = V + ((long)b * NPTS + n) * O;
    float*       on = out + ((long)b * NPTS + n) * ldo;

    for (int o = tid; o < O; o += 256) {
        float mx = -CUDART_INF_F;
#pragma unroll
        for (int k = 0; k < KNN; k++)
            mx = fmaxf(mx, Ub[(long)nb[k] * O + o]);
        float y = mx - un[o] + vn[o];
        float g = bn[o], be = bn[O + o], mm = bn[2 * O + o], vv = bn[3 * O + o];
        float s = g * rsqrtf(vv + EPS);
        y = (y - mm) * s + be;
        on[o] = y > 0.f ? y : 0.2f * y;
    }
}

// ---------------------------------------------------------------------------
// Pooling (max + mean over N), two-stage
// ---------------------------------------------------------------------------
__global__ void __launch_bounds__(256)
pool1_kernel(const float* __restrict__ H5, float* __restrict__ pmax, float* __restrict__ psum)
{
    int b = blockIdx.y, chunk = blockIdx.x;      // PCH chunks of 32 rows
    int tid = threadIdx.x;
    float mx[4] = {-CUDART_INF_F, -CUDART_INF_F, -CUDART_INF_F, -CUDART_INF_F};
    float sm[4] = {0.f, 0.f, 0.f, 0.f};
    const float* h = H5 + ((long)b * NPTS + chunk * 32) * 1024;
    for (int n = 0; n < 32; n++) {
        const float* row = h + (long)n * 1024;
#pragma unroll
        for (int q = 0; q < 4; q++) {
            float v = row[tid + 256 * q];
            mx[q] = fmaxf(mx[q], v);
            sm[q] += v;
        }
    }
#pragma unroll
    for (int q = 0; q < 4; q++) {
        int o = tid + 256 * q;
        pmax[((long)b * PCH + chunk) * 1024 + o] = mx[q];
        psum[((long)b * PCH + chunk) * 1024 + o] = sm[q];
    }
}

__global__ void __launch_bounds__(256)
pool2_kernel(const float* __restrict__ pmax, const float* __restrict__ psum,
             float* __restrict__ pooled)
{
    int b = blockIdx.y;
    int o = blockIdx.x * 256 + threadIdx.x;      // 0..1023
    float mx = -CUDART_INF_F, sm = 0.f;
    for (int c = 0; c < PCH; c++) {
        mx = fmaxf(mx, pmax[((long)b * PCH + c) * 1024 + o]);
        sm += psum[((long)b * PCH + c) * 1024 + o];
    }
    pooled[b * 2048 + o]        = mx;
    pooled[b * 2048 + 1024 + o] = sm * (1.f / NPTS);
}

// ---------------------------------------------------------------------------
// Head:  z = bn_lrelu(pooled @ Wl1^T);  out = z @ Wl3^T + bl3
// ---------------------------------------------------------------------------
__global__ void __launch_bounds__(256)
head1_kernel(const float* __restrict__ pooled, const float* __restrict__ Wl1,
             const float* __restrict__ bn6, float* __restrict__ z)
{
    int b = blockIdx.y, j = blockIdx.x;          // j < 512
    int tid = threadIdx.x;
    const float* p = pooled + b * 2048;
    const float* w = Wl1 + (long)j * 2048;
    float s = 0.f;
    for (int c = tid; c < 2048; c += 256) s += p[c] * w[c];
    __shared__ float red[256];
    red[tid] = s; __syncthreads();
    for (int st = 128; st > 0; st >>= 1) {
        if (tid < st) red[tid] += red[tid + st];
        __syncthreads();
    }
    if (tid == 0) {
        float y = red[0];
        float g = bn6[j], be = bn6[512 + j], mm = bn6[1024 + j], vv = bn6[1536 + j];
        y = (y - mm) * (g * rsqrtf(vv + EPS)) + be;
        z[b * 512 + j] = y > 0.f ? y : 0.2f * y;
    }
}

__global__ void __launch_bounds__(128)
head2_kernel(const float* __restrict__ z, const float* __restrict__ Wl3,
             const float* __restrict__ bl3, float* __restrict__ out)
{
    int b = blockIdx.y, t = blockIdx.x;          // t < 40
    int tid = threadIdx.x;
    const float* zb = z + b * 512;
    const float* w  = Wl3 + (long)t * 512;
    float s = 0.f;
    for (int c = tid; c < 512; c += 128) s += zb[c] * w[c];
    __shared__ float red[128];
    red[tid] = s; __syncthreads();
    for (int st = 64; st > 0; st >>= 1) {
        if (tid < st) red[tid] += red[tid + st];
        __syncthreads();
    }
    if (tid == 0) out[b * 40 + t] = red[0] + bl3[t];
}

// ---------------------------------------------------------------------------
// Host driver
// ---------------------------------------------------------------------------
static void launch_gemm2(const float* A, int lda, long sA,
                         const float* B1, const float* B2, int ldb, long sB,
                         float* C1, float* C2, int ldc, long sC,
                         int M, int N1, int N2, int K,
                         const float* bn, int bnN)
{
    dim3 grid((N1 + N2) / BN, M / BM, BATCH);
    gemm_nt<<<grid, 256>>>(A, lda, sA, B1, B2, ldb, sB, C1, C2, ldc, sC, N1, K, bn, bnN);
}

static void run_edgeconv(const float* Xin, int lda, int Kdim,
                         const float* W, const float* bn, int O,
                         float* Hout, int ldo,
                         float* G, int* idx, float* U, float* V)
{
    // 1) Gram matrix
    launch_gemm2(Xin, lda, (long)NPTS * lda, Xin, Xin, lda, (long)NPTS * lda,
                 G, G, NPTS, (long)NPTS * NPTS, NPTS, NPTS, 0, Kdim, nullptr, 0);
    // 2) top-20 per row
    topk_kernel<<<dim3(NPTS, BATCH), 256>>>(G, idx);
    // 3) fused U = X @ W_left^T and V = X @ W_right^T in one launch
    launch_gemm2(Xin, lda, (long)NPTS * lda, W, W + Kdim, 2 * Kdim, 0,
                 U, V, O, (long)NPTS * O, NPTS, O, O, Kdim, nullptr, 0);
    // 4) gather + max + bn + lrelu
    aggregate_kernel<<<dim3(NPTS, BATCH), 256>>>(U, V, idx, bn, Hout, O, ldo);
}

extern "C" void kernel_launch(void* const* d_in, const int* in_sizes, int n_in,
                              void* d_out, int out_size)
{
    (void)in_sizes; (void)n_in; (void)out_size;
    const float* x   = (const float*)d_in[0];
    const float* W1  = (const float*)d_in[1];
    const float* bn1 = (const float*)d_in[2];
    const float* W2  = (const float*)d_in[3];
    const float* bn2 = (const float*)d_in[4];
    const float* W3  = (const float*)d_in[5];
    const float* bn3 = (const float*)d_in[6];
    const float* W4  = (const float*)d_in[7];
    const float* bn4 = (const float*)d_in[8];
    const float* W5  = (const float*)d_in[9];
    const float* bn5 = (const float*)d_in[10];
    const float* Wl1 = (const float*)d_in[11];
    const float* bn6 = (const float*)d_in[12];
    const float* Wl3 = (const float*)d_in[13];
    const float* bl3 = (const float*)d_in[14];
    float* out = (float*)d_out;

    float *XT, *G, *U, *V, *H, *H5, *pmax, *psum, *pool, *z;
    int* idx;
    cudaGetSymbolAddress((void**)&XT,   g_XT);
    cudaGetSymbolAddress((void**)&G,    g_G);
    cudaGetSymbolAddress((void**)&idx,  g_idx);
    cudaGetSymbolAddress((void**)&U,    g_U);
    cudaGetSymbolAddress((void**)&V,    g_V);
    cudaGetSymbolAddress((void**)&H,    g_H);
    cudaGetSymbolAddress((void**)&H5,   g_H5);
    cudaGetSymbolAddress((void**)&pmax, g_pmax);
    cudaGetSymbolAddress((void**)&psum, g_psum);
    cudaGetSymbolAddress((void**)&pool, g_pool);
    cudaGetSymbolAddress((void**)&z,    g_z);

    // transpose x (B,C,N) -> XT (B,N,C)
    transpose_kernel<<<dim3(NPTS / 32, CIN / 32, BATCH), dim3(32, 8)>>>(x, XT);

    // EdgeConv 1..4, outputs written into slices of H (ld = 1152)
    run_edgeconv(XT,      CIN,  768, W1, bn1, 512, H,       HDIM, G, idx, U, V);
    run_edgeconv(H,       HDIM, 512, W2, bn2, 256, H + 512, HDIM, G, idx, U, V);
    run_edgeconv(H + 512, HDIM, 256, W3, bn3, 128, H + 768, HDIM, G, idx, U, V);
    run_edgeconv(H + 768, HDIM, 128, W4, bn4, 256, H + 896, HDIM, G, idx, U, V);

    // conv5: H (N x 1152) @ W5^T (1152 x 1024) + bn5 + lrelu  -> H5
    launch_gemm2(H, HDIM, (long)NPTS * HDIM, W5, W5, HDIM, 0,
                 H5, H5, 1024, (long)NPTS * 1024, NPTS, 1024, 0, HDIM, bn5, 1024);

    // pooling -> pooled (B x 2048)
    pool1_kernel<<<dim3(PCH, BATCH), 256>>>(H5, pmax, psum);
    pool2_kernel<<<dim3(4, BATCH), 256>>>(pmax, psum, pool);

    // head
    head1_kernel<<<dim3(512, BATCH), 256>>>(pool, Wl1, bn6, z);
    head2_kernel<<<dim3(40, BATCH), 128>>>(z, Wl3, bl3, out);
}

// round 5
// speedup vs baseline: 1.3732x; 1.0174x over previous
#include <cuda_runtime.h>
#include <math_constants.h>

// ---------------------------------------------------------------------------
// Problem constants
// ---------------------------------------------------------------------------
#define BATCH 4
#define NPTS  1024
#define CIN   768
#define KNN   20
#define HDIM  1152    // 512 + 256 + 128 + 256
#define PCH   32      // pooling chunks
#define EPS   1e-5f

// ---------------------------------------------------------------------------
// Scratch (device globals; no allocation allowed)
// ---------------------------------------------------------------------------
__device__ float g_XT [BATCH * NPTS * CIN];     // x transposed: (B, N, C)
__device__ float g_G  [BATCH * NPTS * NPTS];    // gram matrix
__device__ int   g_idx[BATCH * NPTS * KNN];     // knn indices
__device__ float g_U  [BATCH * NPTS * 512];     // W_left  @ x
__device__ float g_V  [BATCH * NPTS * 512];     // W_right @ x
__device__ float g_H  [BATCH * NPTS * HDIM];    // concat(x1,x2,x3,x4)
__device__ float g_H5 [BATCH * NPTS * 1024];    // conv5 output
__device__ float g_pmax[BATCH * PCH * 1024];
__device__ float g_psum[BATCH * PCH * 1024];
__device__ float g_pool[BATCH * 2048];
__device__ float g_z   [BATCH * 512];

// ---------------------------------------------------------------------------
// Packed f32x2 helpers (Blackwell): each lane is an independent rn-rounded
// fp32 op -> bit-identical per output to scalar FFMA.
// ---------------------------------------------------------------------------
static __device__ __forceinline__ unsigned long long pk2(float x, float y) {
    unsigned long long r;
    asm("mov.b64 %0, {%1, %2};" : "=l"(r) : "f"(x), "f"(y));
    return r;
}
static __device__ __forceinline__ void upk2(unsigned long long v, float& x, float& y) {
    asm("mov.b64 {%0, %1}, %2;" : "=f"(x), "=f"(y) : "l"(v));
}
static __device__ __forceinline__ void ffma2(unsigned long long& d,
                                             unsigned long long a,
                                             unsigned long long b) {
    asm("fma.rn.f32x2 %0, %1, %2, %0;" : "+l"(d) : "l"(a), "l"(b));
}

// ---------------------------------------------------------------------------
// Transpose: x (B, C, N) -> XT (B, N, C)
// ---------------------------------------------------------------------------
__global__ void transpose_kernel(const float* __restrict__ x, float* __restrict__ xt) {
    __shared__ float tile[32][33];
    int b  = blockIdx.z;
    int c0 = blockIdx.y * 32;
    int n0 = blockIdx.x * 32;
    const float* xb  = x  + (long)b * CIN * NPTS;
    float*       xtb = xt + (long)b * NPTS * CIN;
    int tx = threadIdx.x, ty = threadIdx.y;            // 32 x 8
#pragma unroll
    for (int i = 0; i < 32; i += 8)
        tile[ty + i][tx] = xb[(long)(c0 + ty + i) * NPTS + n0 + tx];
    __syncthreads();
#pragma unroll
    for (int i = 0; i < 32; i += 8)
        xtb[(long)(n0 + ty + i) * CIN + c0 + tx] = tile[tx][ty + i];
}

// ---------------------------------------------------------------------------
// Tiled SGEMM with dual-source N split:
//   blocks with n0 <  N1 compute C1 = A * B1^T
//   blocks with n0 >= N1 compute C2 = A * B2^T  (column n0-N1)
// 128x128 tiles, 8x8 per-thread outputs via packed fma.rn.f32x2 (row pairs),
// double-buffered smem, 256 threads.
// k accumulation sequential per output -> bit-identical to scalar FFMA chain.
// sym != 0: only compute blocks bx <= by (Gram symmetry; mirror separately).
// Optional epilogue: batchnorm + leaky_relu(0.2).
// Requirements: M % 128 == 0, N % 128 == 0, K % 16 == 0
// ---------------------------------------------------------------------------
#define BM 128
#define BN 128
#define BK 16

__global__ void __launch_bounds__(256, 2)
gemm_nt(const float* __restrict__ A, int lda, long strideA,
        const float* __restrict__ B1, const float* __restrict__ B2,
        int ldb, long strideB,
        float* __restrict__ C1, float* __restrict__ C2,
        int ldc, long strideC,
        int N1, int K,
        const float* __restrict__ bn, int bnN, int sym)
{
    if (sym && (int)blockIdx.x > (int)blockIdx.y) return;

    __shared__ __align__(16) float As[2][BK][BM];
    __shared__ __align__(16) float Bs[2][BK][BN];

    const int bz = blockIdx.z;
    const int m0 = blockIdx.y * BM;
    const int nb0 = blockIdx.x * BN;

    const float* Bsel;
    float*       Csel;
    int n0;
    if (nb0 < N1) { Bsel = B1; Csel = C1; n0 = nb0; }
    else          { Bsel = B2; Csel = C2; n0 = nb0 - N1; }

    const float* Ab = A    + (long)bz * strideA;
    const float* Bb = Bsel + (long)bz * strideB;
    float*       Cb = Csel + (long)bz * strideC;

    const int tid = threadIdx.x;
    // loader mapping: rows lr and lr+64, 4 k-values each
    const int lr = tid >> 2;            // 0..63
    const int lc = (tid & 3) * 4;       // 0,4,8,12
    // compute mapping: 16x16 thread grid; each thread 8 rows x 8 cols
    const int ty = tid >> 4;            // 0..15
    const int tx = tid & 15;            // 0..15

    unsigned long long acc[4][8];       // row-pairs (2rp, 2rp+1) x 8 cols
#pragma unroll
    for (int i = 0; i < 4; i++)
#pragma unroll
        for (int j = 0; j < 8; j++) acc[i][j] = 0ull;

    const int nTiles = K / BK;
    float4 pa0, pa1, pb0, pb1;

    // prefetch tile 0
    pa0 = *reinterpret_cast<const float4*>(&Ab[(long)(m0 + lr)      * lda + lc]);
    pa1 = *reinterpret_cast<const float4*>(&Ab[(long)(m0 + lr + 64) * lda + lc]);
    pb0 = *reinterpret_cast<const float4*>(&Bb[(long)(n0 + lr)      * ldb + lc]);
    pb1 = *reinterpret_cast<const float4*>(&Bb[(long)(n0 + lr + 64) * ldb + lc]);
    As[0][lc + 0][lr] = pa0.x; As[0][lc + 1][lr] = pa0.y;
    As[0][lc + 2][lr] = pa0.z; As[0][lc + 3][lr] = pa0.w;
    As[0][lc + 0][lr + 64] = pa1.x; As[0][lc + 1][lr + 64] = pa1.y;
    As[0][lc + 2][lr + 64] = pa1.z; As[0][lc + 3][lr + 64] = pa1.w;
    Bs[0][lc + 0][lr] = pb0.x; Bs[0][lc + 1][lr] = pb0.y;
    Bs[0][lc + 2][lr] = pb0.z; Bs[0][lc + 3][lr] = pb0.w;
    Bs[0][lc + 0][lr + 64] = pb1.x; Bs[0][lc + 1][lr + 64] = pb1.y;
    Bs[0][lc + 2][lr + 64] = pb1.z; Bs[0][lc + 3][lr + 64] = pb1.w;
    __syncthreads();

    for (int t = 0; t < nTiles; t++) {
        const int cur = t & 1;
        if (t + 1 < nTiles) {
            const int k0 = (t + 1) * BK;
            pa0 = *reinterpret_cast<const float4*>(&Ab[(long)(m0 + lr)      * lda + k0 + lc]);
            pa1 = *reinterpret_cast<const float4*>(&Ab[(long)(m0 + lr + 64) * lda + k0 + lc]);
            pb0 = *reinterpret_cast<const float4*>(&Bb[(long)(n0 + lr)      * ldb + k0 + lc]);
            pb1 = *reinterpret_cast<const float4*>(&Bb[(long)(n0 + lr + 64) * ldb + k0 + lc]);
        }

#pragma unroll
        for (int k = 0; k < BK; k++) {
            // a: 8 rows as 4 packed pairs (free reinterpret of float4 pairs)
            ulonglong2 ap01 = *reinterpret_cast<const ulonglong2*>(&As[cur][k][ty * 8]);
            ulonglong2 ap23 = *reinterpret_cast<const ulonglong2*>(&As[cur][k][ty * 8 + 4]);
            float4 b0 = *reinterpret_cast<const float4*>(&Bs[cur][k][tx * 8]);
            float4 b1 = *reinterpret_cast<const float4*>(&Bs[cur][k][tx * 8 + 4]);
            unsigned long long ap[4] = {ap01.x, ap01.y, ap23.x, ap23.y};
            unsigned long long bd[8] = {
                pk2(b0.x, b0.x), pk2(b0.y, b0.y), pk2(b0.z, b0.z), pk2(b0.w, b0.w),
                pk2(b1.x, b1.x), pk2(b1.y, b1.y), pk2(b1.z, b1.z), pk2(b1.w, b1.w)};
#pragma unroll
            for (int rp = 0; rp < 4; rp++)
#pragma unroll
                for (int j = 0; j < 8; j++)
                    ffma2(acc[rp][j], ap[rp], bd[j]);
        }

        if (t + 1 < nTiles) {
            const int nxt = 1 - cur;
            As[nxt][lc + 0][lr] = pa0.x; As[nxt][lc + 1][lr] = pa0.y;
            As[nxt][lc + 2][lr] = pa0.z; As[nxt][lc + 3][lr] = pa0.w;
            As[nxt][lc + 0][lr + 64] = pa1.x; As[nxt][lc + 1][lr + 64] = pa1.y;
            As[nxt][lc + 2][lr + 64] = pa1.z; As[nxt][lc + 3][lr + 64] = pa1.w;
            Bs[nxt][lc + 0][lr] = pb0.x; Bs[nxt][lc + 1][lr] = pb0.y;
            Bs[nxt][lc + 2][lr] = pb0.z; Bs[nxt][lc + 3][lr] = pb0.w;
            Bs[nxt][lc + 0][lr + 64] = pb1.x; Bs[nxt][lc + 1][lr + 64] = pb1.y;
            Bs[nxt][lc + 2][lr + 64] = pb1.z; Bs[nxt][lc + 3][lr + 64] = pb1.w;
        }
        __syncthreads();
    }

    // epilogue
    const int cm = m0 + ty * 8;
    const int cn = n0 + tx * 8;
    float sc[8], sh[8];
    if (bn) {
#pragma unroll
        for (int j = 0; j < 8; j++) {
            int n = cn + j;
            float g = bn[n], b = bn[bnN + n], m = bn[2 * bnN + n], v = bn[3 * bnN + n];
            sc[j] = g * rsqrtf(v + EPS);
            sh[j] = b - m * sc[j];
        }
    }
#pragma unroll
    for (int rp = 0; rp < 4; rp++) {
        float lo[8], hi[8];
#pragma unroll
        for (int j = 0; j < 8; j++) upk2(acc[rp][j], lo[j], hi[j]);
        if (bn) {
#pragma unroll
            for (int j = 0; j < 8; j++) {
                float v0 = lo[j] * sc[j] + sh[j];
                float v1 = hi[j] * sc[j] + sh[j];
                lo[j] = v0 > 0.f ? v0 : 0.2f * v0;
                hi[j] = v1 > 0.f ? v1 : 0.2f * v1;
            }
        }
        long r0 = (long)(cm + rp * 2) * ldc + cn;
        long r1 = r0 + ldc;
        *reinterpret_cast<float4*>(&Cb[r0])     = make_float4(lo[0], lo[1], lo[2], lo[3]);
        *reinterpret_cast<float4*>(&Cb[r0 + 4]) = make_float4(lo[4], lo[5], lo[6], lo[7]);
        *reinterpret_cast<float4*>(&Cb[r1])     = make_float4(hi[0], hi[1], hi[2], hi[3]);
        *reinterpret_cast<float4*>(&Cb[r1 + 4]) = make_float4(hi[4], hi[5], hi[6], hi[7]);
    }
}

// ---------------------------------------------------------------------------
// Gram mirror: fill G[n][m] (m >= 128*((n>>7)+1)) from G[m][n].
// Bit-identical because FMA(a,b,c) == FMA(b,a,c) with same k order.
// ---------------------------------------------------------------------------
__global__ void mirror_kernel(float* __restrict__ G)
{
    int b  = blockIdx.z;
    int m0 = blockIdx.x * 32;   // destination cols
    int n0 = blockIdx.y * 32;   // destination rows
    if (m0 < 128 * ((n0 >> 7) + 1)) return;   // tile already computed

    __shared__ float tile[32][33];
    float* Gb = G + (long)b * NPTS * NPTS;
    int tx = threadIdx.x, ty = threadIdx.y;    // 32 x 8
#pragma unroll
    for (int i = 0; i < 32; i += 8)
        tile[ty + i][tx] = Gb[(long)(m0 + ty + i) * NPTS + n0 + tx];
    __syncthreads();
#pragma unroll
    for (int i = 0; i < 32; i += 8)
        Gb[(long)(n0 + ty + i) * NPTS + m0 + tx] = tile[tx][ty + i];
}

// ---------------------------------------------------------------------------
// Top-K (K=20) per row of the Gram matrix, warp-shuffle reductions.
// ordering key: 2*G[n][m] - G[m][m]   (constant -||x_n||^2 dropped)
// tie-break: lower index (matches jax.lax.top_k)
// ---------------------------------------------------------------------------
__global__ void __launch_bounds__(256)
topk_kernel(const float* __restrict__ G, int* __restrict__ idx)
{
    int b = blockIdx.y;
    int n = blockIdx.x;
    const float* Gb = G + ((long)b * NPTS + n) * NPTS;
    const float* Gd = G + (long)b * NPTS * NPTS;

    __shared__ float key[NPTS];
    __shared__ float wv[8];
    __shared__ int   wi[8];
    int tid = threadIdx.x;
    int lane = tid & 31, wid = tid >> 5;

    for (int m = tid; m < NPTS; m += 256)
        key[m] = 2.f * Gb[m] - Gd[(long)m * NPTS + m];
    __syncthreads();

    for (int it = 0; it < KNN; ++it) {
        float bv = -CUDART_INF_F;
        int   bi = 0x7fffffff;
#pragma unroll
        for (int q = 0; q < 4; q++) {
            int m = tid + 256 * q;
            float v = key[m];
            if (v > bv) { bv = v; bi = m; }   // increasing m: strict > keeps lowest idx
        }
#pragma unroll
        for (int off = 16; off > 0; off >>= 1) {
            float ov = __shfl_down_sync(0xffffffffu, bv, off);
            int   oi = __shfl_down_sync(0xffffffffu, bi, off);
            if (ov > bv || (ov == bv && oi < bi)) { bv = ov; bi = oi; }
        }
        if (lane == 0) { wv[wid] = bv; wi[wid] = bi; }
        __syncthreads();
        if (wid == 0) {
            bv = (lane < 8) ? wv[lane] : -CUDART_INF_F;
            bi = (lane < 8) ? wi[lane] : 0x7fffffff;
#pragma unroll
            for (int off = 4; off > 0; off >>= 1) {
                float ov = __shfl_down_sync(0xffffffffu, bv, off);
                int   oi = __shfl_down_sync(0xffffffffu, bi, off);
                if (ov > bv || (ov == bv && oi < bi)) { bv = ov; bi = oi; }
            }
            if (lane == 0) {
                idx[((long)b * NPTS + n) * KNN + it] = bi;
                key[bi] = -CUDART_INF_F;
            }
        }
        __syncthreads();
    }
}

// ---------------------------------------------------------------------------
// EdgeConv aggregation:
// out[n][o] = bn_lrelu( max_k U[idx[n,k]][o]  -  U[n][o] + V[n][o] )
// (valid because bn scale > 0 and leaky_relu are monotone increasing)
// ---------------------------------------------------------------------------
__global__ void __launch_bounds__(256)
aggregate_kernel(const float* __restrict__ U, const float* __restrict__ V,
                 const int* __restrict__ idx, const float* __restrict__ bn,
                 float* __restrict__ out, int O, int ldo)
{
    int b = blockIdx.y, n = blockIdx.x;
    __shared__ int nb[KNN];
    int tid = threadIdx.x;
    if (tid < KNN) nb[tid] = idx[((long)b * NPTS + n) * KNN + tid];
    __syncthreads();

    const float* Ub = U + (long)b * NPTS * O;
    const float* un = Ub + (long)n * O;
    const float* vn = V + ((long)b * NPTS + n) * O;
    float*       on = out + ((long)b * NPTS + n) * ldo;

    for (int o = tid; o < O; o += 256) {
        float mx = -CUDART_INF_F;
#pragma unroll
        for (int k = 0; k < KNN; k++)
            mx = fmaxf(mx, Ub[(long)nb[k] * O + o]);
        float y = mx - un[o] + vn[o];
        float g = bn[o], be = bn[O + o], mm = bn[2 * O + o], vv = bn[3 * O + o];
        float s = g * rsqrtf(vv + EPS);
        y = (y - mm) * s + be;
        on[o] = y > 0.f ? y : 0.2f * y;
    }
}

// ---------------------------------------------------------------------------
// Pooling (max + mean over N), two-stage
// ---------------------------------------------------------------------------
__global__ void __launch_bounds__(256)
pool1_kernel(const float* __restrict__ H5, float* __restrict__ pmax, float* __restrict__ psum)
{
    int b = blockIdx.y, chunk = blockIdx.x;      // PCH chunks of 32 rows
    int tid = threadIdx.x;
    float mx[4] = {-CUDART_INF_F, -CUDART_INF_F, -CUDART_INF_F, -CUDART_INF_F};
    float sm[4] = {0.f, 0.f, 0.f, 0.f};
    const float* h = H5 + ((long)b * NPTS + chunk * 32) * 1024;
    for (int n = 0; n < 32; n++) {
        const float* row = h + (long)n * 1024;
#pragma unroll
        for (int q = 0; q < 4; q++) {
            float v = row[tid + 256 * q];
            mx[q] = fmaxf(mx[q], v);
            sm[q] += v;
        }
    }
#pragma unroll
    for (int q = 0; q < 4; q++) {
        int o = tid + 256 * q;
        pmax[((long)b * PCH + chunk) * 1024 + o] = mx[q];
        psum[((long)b * PCH + chunk) * 1024 + o] = sm[q];
    }
}

__global__ void __launch_bounds__(256)
pool2_kernel(const float* __restrict__ pmax, const float* __restrict__ psum,
             float* __restrict__ pooled)
{
    int b = blockIdx.y;
    int o = blockIdx.x * 256 + threadIdx.x;      // 0..1023
    float mx = -CUDART_INF_F, sm = 0.f;
    for (int c = 0; c < PCH; c++) {
        mx = fmaxf(mx, pmax[((long)b * PCH + c) * 1024 + o]);
        sm += psum[((long)b * PCH + c) * 1024 + o];
    }
    pooled[b * 2048 + o]        = mx;
    pooled[b * 2048 + 1024 + o] = sm * (1.f / NPTS);
}

// ---------------------------------------------------------------------------
// Head:  z = bn_lrelu(pooled @ Wl1^T);  out = z @ Wl3^T + bl3
// ---------------------------------------------------------------------------
__global__ void __launch_bounds__(256)
head1_kernel(const float* __restrict__ pooled, const float* __restrict__ Wl1,
             const float* __restrict__ bn6, float* __restrict__ z)
{
    int b = blockIdx.y, j = blockIdx.x;          // j < 512
    int tid = threadIdx.x;
    const float* p = pooled + b * 2048;
    const float* w = Wl1 + (long)j * 2048;
    float s = 0.f;
    for (int c = tid; c < 2048; c += 256) s += p[c] * w[c];
    __shared__ float red[256];
    red[tid] = s; __syncthreads();
    for (int st = 128; st > 0; st >>= 1) {
        if (tid < st) red[tid] += red[tid + st];
        __syncthreads();
    }
    if (tid == 0) {
        float y = red[0];
        float g = bn6[j], be = bn6[512 + j], mm = bn6[1024 + j], vv = bn6[1536 + j];
        y = (y - mm) * (g * rsqrtf(vv + EPS)) + be;
        z[b * 512 + j] = y > 0.f ? y : 0.2f * y;
    }
}

__global__ void __launch_bounds__(128)
head2_kernel(const float* __restrict__ z, const float* __restrict__ Wl3,
             const float* __restrict__ bl3, float* __restrict__ out)
{
    int b = blockIdx.y, t = blockIdx.x;          // t < 40
    int tid = threadIdx.x;
    const float* zb = z + b * 512;
    const float* w  = Wl3 + (long)t * 512;
    float s = 0.f;
    for (int c = tid; c < 512; c += 128) s += zb[c] * w[c];
    __shared__ float red[128];
    red[tid] = s; __syncthreads();
    for (int st = 64; st > 0; st >>= 1) {
        if (tid < st) red[tid] += red[tid + st];
        __syncthreads();
    }
    if (tid == 0) out[b * 40 + t] = red[0] + bl3[t];
}

// ---------------------------------------------------------------------------
// Host driver
// ---------------------------------------------------------------------------
static void launch_gemm2(const float* A, int lda, long sA,
                         const float* B1, const float* B2, int ldb, long sB,
                         float* C1, float* C2, int ldc, long sC,
                         int M, int N1, int N2, int K,
                         const float* bn, int bnN, int sym)
{
    dim3 grid((N1 + N2) / BN, M / BM, BATCH);
    gemm_nt<<<grid, 256>>>(A, lda, sA, B1, B2, ldb, sB, C1, C2, ldc, sC, N1, K, bn, bnN, sym);
}

static void run_edgeconv(const float* Xin, int lda, int Kdim,
                         const float* W, const float* bn, int O,
                         float* Hout, int ldo,
                         float* G, int* idx, float* U, float* V)
{
    // 1) Gram matrix, lower-triangular blocks only, then mirror
    launch_gemm2(Xin, lda, (long)NPTS * lda, Xin, Xin, lda, (long)NPTS * lda,
                 G, G, NPTS, (long)NPTS * NPTS, NPTS, NPTS, 0, Kdim, nullptr, 0, 1);
    mirror_kernel<<<dim3(NPTS / 32, NPTS / 32, BATCH), dim3(32, 8)>>>(G);
    // 2) top-20 per row
    topk_kernel<<<dim3(NPTS, BATCH), 256>>>(G, idx);
    // 3) fused U = X @ W_left^T and V = X @ W_right^T in one launch
    launch_gemm2(Xin, lda, (long)NPTS * lda, W, W + Kdim, 2 * Kdim, 0,
                 U, V, O, (long)NPTS * O, NPTS, O, O, Kdim, nullptr, 0, 0);
    // 4) gather + max + bn + lrelu
    aggregate_kernel<<<dim3(NPTS, BATCH), 256>>>(U, V, idx, bn, Hout, O, ldo);
}

extern "C" void kernel_launch(void* const* d_in, const int* in_sizes, int n_in,
                              void* d_out, int out_size)
{
    (void)in_sizes; (void)n_in; (void)out_size;
    const float* x   = (const float*)d_in[0];
    const float* W1  = (const float*)d_in[1];
    const float* bn1 = (const float*)d_in[2];
    const float* W2  = (const float*)d_in[3];
    const float* bn2 = (const float*)d_in[4];
    const float* W3  = (const float*)d_in[5];
    const float* bn3 = (const float*)d_in[6];
    const float* W4  = (const float*)d_in[7];
    const float* bn4 = (const float*)d_in[8];
    const float* W5  = (const float*)d_in[9];
    const float* bn5 = (const float*)d_in[10];
    const float* Wl1 = (const float*)d_in[11];
    const float* bn6 = (const float*)d_in[12];
    const float* Wl3 = (const float*)d_in[13];
    const float* bl3 = (const float*)d_in[14];
    float* out = (float*)d_out;

    float *XT, *G, *U, *V, *H, *H5, *pmax, *psum, *pool, *z;
    int* idx;
    cudaGetSymbolAddress((void**)&XT,   g_XT);
    cudaGetSymbolAddress((void**)&G,    g_G);
    cudaGetSymbolAddress((void**)&idx,  g_idx);
    cudaGetSymbolAddress((void**)&U,    g_U);
    cudaGetSymbolAddress((void**)&V,    g_V);
    cudaGetSymbolAddress((void**)&H,    g_H);
    cudaGetSymbolAddress((void**)&H5,   g_H5);
    cudaGetSymbolAddress((void**)&pmax, g_pmax);
    cudaGetSymbolAddress((void**)&psum, g_psum);
    cudaGetSymbolAddress((void**)&pool, g_pool);
    cudaGetSymbolAddress((void**)&z,    g_z);

    // transpose x (B,C,N) -> XT (B,N,C)
    transpose_kernel<<<dim3(NPTS / 32, CIN / 32, BATCH), dim3(32, 8)>>>(x, XT);

    // EdgeConv 1..4, outputs written into slices of H (ld = 1152)
    run_edgeconv(XT,      CIN,  768, W1, bn1, 512, H,       HDIM, G, idx, U, V);
    run_edgeconv(H,       HDIM, 512, W2, bn2, 256, H + 512, HDIM, G, idx, U, V);
    run_edgeconv(H + 512, HDIM, 256, W3, bn3, 128, H + 768, HDIM, G, idx, U, V);
    run_edgeconv(H + 768, HDIM, 128, W4, bn4, 256, H + 896, HDIM, G, idx, U, V);

    // conv5: H (N x 1152) @ W5^T (1152 x 1024) + bn5 + lrelu  -> H5
    launch_gemm2(H, HDIM, (long)NPTS * HDIM, W5, W5, HDIM, 0,
                 H5, H5, 1024, (long)NPTS * 1024, NPTS, 1024, 0, HDIM, bn5, 1024, 0);

    // pooling -> pooled (B x 2048)
    pool1_kernel<<<dim3(PCH, BATCH), 256>>>(H5, pmax, psum);
    pool2_kernel<<<dim3(4, BATCH), 256>>>(pmax, psum, pool);

    // head
    head1_kernel<<<dim3(512, BATCH), 256>>>(pool, Wl1, bn6, z);
    head2_kernel<<<dim3(40, BATCH), 128>>>(z, Wl3, bl3, out);
}